// round 1
// baseline (speedup 1.0000x reference)
#include <cuda_runtime.h>
#include <cstdint>
#include <cstddef>

// Problem constants
#define TT   512
#define BB   32
#define HH   1024
#define G4H  4096          // 4*HH
#define NBLK 128           // persistent recurrent grid (<= 148 SMs -> co-resident)

// ---------------- scratch (static __device__ globals; no allocations) ----------------
__device__ float g_xg[(size_t)TT * BB * G4H];   // 256 MB: input projection for current layer
__device__ float g_x1[(size_t)TT * BB * HH];    // 64 MB: layer-0 output (input to layer-1 GEMM)
__device__ float g_hbuf[2][BB * HH];            // ping-pong hidden state
__device__ unsigned int          g_bar_count;
__device__ volatile unsigned int g_bar_gen;

__device__ __forceinline__ float sigm(float x) {
    return 1.0f / (1.0f + expf(-x));
}

// Classic gen-counter grid barrier. All NBLK blocks are co-resident (NBLK < #SMs).
__device__ __forceinline__ void grid_barrier() {
    __syncthreads();
    if (threadIdx.x == 0) {
        __threadfence();
        unsigned int g = g_bar_gen;
        if (atomicAdd(&g_bar_count, 1u) == NBLK - 1u) {
            atomicExch(&g_bar_count, 0u);
            __threadfence();
            g_bar_gen = g + 1u;
        } else {
            while (g_bar_gen == g) { }
        }
        __threadfence();
    }
    __syncthreads();
}

// ---------------- input projection GEMM: Y[m][n] = sum_k X[m][k]*W[n][k] + bi[n] ----------------
// M=16384, N=4096, K=1024. Both X and W are K-major ("NT" layout). Tile 128x64x16, 256 thr, 8x4/thread.
#define GBM 128
#define GBN 64
#define GBK 16

__global__ void __launch_bounds__(256) gemm_xw_kernel(
    const float* __restrict__ X, const float* __restrict__ W,
    const float* __restrict__ bi, float* __restrict__ Y)
{
    __shared__ float As[GBK][132];   // [k][m], padded
    __shared__ float Bs[GBK][68];    // [k][n], padded

    const int tid = threadIdx.x;
    const int n0  = blockIdx.x * GBN;
    const int m0  = blockIdx.y * GBM;
    const int tn  = tid & 15;        // 0..15 -> 4 n each
    const int tm  = tid >> 4;        // 0..15 -> 8 m each

    float acc[8][4];
#pragma unroll
    for (int i = 0; i < 8; ++i)
#pragma unroll
        for (int j = 0; j < 4; ++j) acc[i][j] = 0.0f;

    for (int k0 = 0; k0 < HH; k0 += GBK) {
        // Load A tile: 128 rows x 16 k  (2 float4 per thread, transposed store)
#pragma unroll
        for (int r = 0; r < 2; ++r) {
            int idx = r * 256 + tid;
            int m   = idx >> 2;
            int kq  = (idx & 3) * 4;
            float4 v = *(const float4*)(X + (size_t)(m0 + m) * HH + k0 + kq);
            As[kq + 0][m] = v.x; As[kq + 1][m] = v.y;
            As[kq + 2][m] = v.z; As[kq + 3][m] = v.w;
        }
        // Load B tile: 64 rows x 16 k (1 float4 per thread)
        {
            int n  = tid >> 2;
            int kq = (tid & 3) * 4;
            float4 v = *(const float4*)(W + (size_t)(n0 + n) * HH + k0 + kq);
            Bs[kq + 0][n] = v.x; Bs[kq + 1][n] = v.y;
            Bs[kq + 2][n] = v.z; Bs[kq + 3][n] = v.w;
        }
        __syncthreads();

#pragma unroll
        for (int k = 0; k < GBK; ++k) {
            float4 a0 = *(const float4*)&As[k][tm * 8];
            float4 a1 = *(const float4*)&As[k][tm * 8 + 4];
            float4 b  = *(const float4*)&Bs[k][tn * 4];
            float am[8] = {a0.x, a0.y, a0.z, a0.w, a1.x, a1.y, a1.z, a1.w};
            float bn[4] = {b.x, b.y, b.z, b.w};
#pragma unroll
            for (int i = 0; i < 8; ++i)
#pragma unroll
                for (int j = 0; j < 4; ++j)
                    acc[i][j] += am[i] * bn[j];
        }
        __syncthreads();
    }

    float4 bv = *(const float4*)(bi + n0 + tn * 4);
#pragma unroll
    for (int i = 0; i < 8; ++i) {
        float4 o;
        o.x = acc[i][0] + bv.x;
        o.y = acc[i][1] + bv.y;
        o.z = acc[i][2] + bv.z;
        o.w = acc[i][3] + bv.w;
        *(float4*)(Y + (size_t)(m0 + tm * 8 + i) * G4H + n0 + tn * 4) = o;
    }
}

// ---------------- persistent recurrent kernel (one launch = all 512 steps of one layer) --------
// Block b owns n in [n0, n0+8) and the 32 gate rows {g*H + n : g in 0..3}.
// Per step: 32b x 32j x 1024k GEMM (smem-tiled), sigmoid, local c/h update, grid barrier.
__global__ void __launch_bounds__(256) recurrent_kernel(
    const float* __restrict__ xg,   // [T][B][4H]
    const float* __restrict__ R,    // [4H][H]
    const float* __restrict__ bh,   // [4H]
    const float* __restrict__ h0,   // [B][H]
    const float* __restrict__ c0,   // [B][H]
    float* __restrict__ out,        // [T][B][H]
    float* __restrict__ hT,         // [B][H]
    float* __restrict__ cT)         // [B][H]
{
    __shared__ float hs[32 * 34];     // [k][b], padded stride 34 (keeps float2 aligned)
    __shared__ float Rs[32 * 34];     // [k][j'], padded
    __shared__ float gbuf[32 * 33];   // [j'][b]

    const int tid = threadIdx.x;
    const int n0  = blockIdx.x * 8;

    // GEMM-phase thread mapping: 16x16 grid, thread covers b in {2tb,2tb+1}, j' in {2tj,2tj+1}
    const int tj = tid & 15;
    const int tb = tid >> 4;

    // Load-phase mapping for 32x32 chunks: float4 along k
    const int lk = (tid & 7) * 4;   // k offset within chunk
    const int lr = tid >> 3;        // row (b for hs, j' for Rs), 0..31
    const int jrow_l = ((lr >> 3) * HH) + n0 + (lr & 7);  // global R row for j'=lr

    // Update-phase mapping: thread -> (b, ni)
    const int ub = tid >> 3;        // b 0..31
    const int un = tid & 7;         // ni 0..7

    // Accumulator gate columns (j'=2tj, 2tj+1 stay within one gate group since 2tj&7 <= 6)
    const int j0  = 2 * tj;
    const int jg0 = (j0 >> 3) * HH + n0 + (j0 & 7);   // global column in [0,4H)
    const float bh0v = bh[jg0];
    const float bh1v = bh[jg0 + 1];

    float creg = c0[ub * HH + n0 + un];

    for (int t = 0; t < TT; ++t) {
        const float* hprev = (t == 0) ? h0 : g_hbuf[t & 1];
        float* hnext = g_hbuf[(t + 1) & 1];

        // init accumulators with xg[t] + bh
        const float* xgt = xg + (size_t)t * BB * G4H;
        float2 x0 = *(const float2*)(xgt + (size_t)(2 * tb) * G4H + jg0);
        float2 x1 = *(const float2*)(xgt + (size_t)(2 * tb + 1) * G4H + jg0);
        float a00 = x0.x + bh0v, a01 = x0.y + bh1v;
        float a10 = x1.x + bh0v, a11 = x1.y + bh1v;

        for (int k0 = 0; k0 < HH; k0 += 32) {
            float4 hv = *(const float4*)(hprev + (size_t)lr * HH + k0 + lk);
            float4 rv = *(const float4*)(R + (size_t)jrow_l * HH + k0 + lk);
            hs[(lk + 0) * 34 + lr] = hv.x; hs[(lk + 1) * 34 + lr] = hv.y;
            hs[(lk + 2) * 34 + lr] = hv.z; hs[(lk + 3) * 34 + lr] = hv.w;
            Rs[(lk + 0) * 34 + lr] = rv.x; Rs[(lk + 1) * 34 + lr] = rv.y;
            Rs[(lk + 2) * 34 + lr] = rv.z; Rs[(lk + 3) * 34 + lr] = rv.w;
            __syncthreads();
#pragma unroll
            for (int k = 0; k < 32; ++k) {
                float2 hh2 = *(const float2*)(hs + k * 34 + 2 * tb);
                float2 rr2 = *(const float2*)(Rs + k * 34 + 2 * tj);
                a00 += hh2.x * rr2.x; a01 += hh2.x * rr2.y;
                a10 += hh2.y * rr2.x; a11 += hh2.y * rr2.y;
            }
            __syncthreads();
        }

        // gates -> smem exchange
        gbuf[(j0)     * 33 + 2 * tb]     = sigm(a00);
        gbuf[(j0 + 1) * 33 + 2 * tb]     = sigm(a01);
        gbuf[(j0)     * 33 + 2 * tb + 1] = sigm(a10);
        gbuf[(j0 + 1) * 33 + 2 * tb + 1] = sigm(a11);
        __syncthreads();

        // local state update: gates order i, o, z, f
        float ig = gbuf[(0 * 8 + un) * 33 + ub];
        float og = gbuf[(1 * 8 + un) * 33 + ub];
        float zg = gbuf[(2 * 8 + un) * 33 + ub];
        float fg = gbuf[(3 * 8 + un) * 33 + ub];
        creg = creg * fg + zg - ig;
        float hval = sigm(creg) - og;

        out[((size_t)t * BB + ub) * HH + n0 + un] = hval;
        hnext[ub * HH + n0 + un] = hval;
        if (t == TT - 1) {
            hT[ub * HH + n0 + un] = hval;
            cT[ub * HH + n0 + un] = creg;
        }

        grid_barrier();   // h visible to all blocks; safe to reuse buffers next step
    }
}

// ---------------- launch ----------------
extern "C" void kernel_launch(void* const* d_in, const int* in_sizes, int n_in,
                              void* d_out, int out_size)
{
    (void)in_sizes; (void)n_in; (void)out_size;
    const float* x   = (const float*)d_in[0];   // [T][B][I]
    const float* h0  = (const float*)d_in[1];   // [L][B][H]
    const float* c0  = (const float*)d_in[2];   // [L][B][H]
    const float* W0  = (const float*)d_in[3];   // [4H][I]
    const float* R0  = (const float*)d_in[4];   // [4H][H]
    const float* bi0 = (const float*)d_in[5];   // [4H]
    const float* bh0 = (const float*)d_in[6];   // [4H]
    const float* W1  = (const float*)d_in[7];   // [4H][H]
    const float* R1  = (const float*)d_in[8];   // [4H][H]
    const float* bi1 = (const float*)d_in[9];   // [4H]
    const float* bh1 = (const float*)d_in[10];  // [4H]

    float* out = (float*)d_out;                       // [T][B][H]
    float* hT  = out + (size_t)TT * BB * HH;          // [L][B][H]
    float* cT  = hT + (size_t)2 * BB * HH;            // [L][B][H]

    float* xg = nullptr;  cudaGetSymbolAddress((void**)&xg, g_xg);
    float* x1 = nullptr;  cudaGetSymbolAddress((void**)&x1, g_x1);

    dim3 ggrid(G4H / GBN, (TT * BB) / GBM);   // 64 x 128

    // Layer 0
    gemm_xw_kernel<<<ggrid, 256>>>(x, W0, bi0, xg);
    recurrent_kernel<<<NBLK, 256>>>(xg, R0, bh0, h0, c0, x1, hT, cT);
    // Layer 1
    gemm_xw_kernel<<<ggrid, 256>>>(x1, W1, bi1, xg);
    recurrent_kernel<<<NBLK, 256>>>(xg, R1, bh1, h0 + BB * HH, c0 + BB * HH,
                                    out, hT + BB * HH, cT + BB * HH);
}

// round 4
// speedup vs baseline: 3.0586x; 3.0586x over previous
#include <cuda_runtime.h>
#include <cstdint>
#include <cstddef>

// Problem constants
#define TT   512
#define BB   32
#define HH   1024
#define G4H  4096
#define NBLK 128           // persistent recurrent grid (co-resident)

// ---------------- scratch ----------------
__device__ float g_xg[(size_t)TT * BB * G4H];   // input projection for current layer
__device__ float g_x1[(size_t)TT * BB * HH];    // layer-0 output
__device__ float g_hbuf[2][BB * HH];            // ping-pong hidden state
__device__ unsigned int          g_cnt1[8 * 32];  // level-1 counters, 128B apart
__device__ unsigned int          g_cnt2;
__device__ volatile unsigned int g_gen;

__device__ __forceinline__ float sigm(float x) {
    return 1.0f / (1.0f + expf(-x));
}

// fp32 -> tf32 (round-to-nearest), returned as raw bits for mma operands
__device__ __forceinline__ uint32_t f2t(float x) {
    uint32_t r;
    asm("cvt.rna.tf32.f32 %0, %1;" : "=r"(r) : "f"(x));
    return r;
}

__device__ __forceinline__ void mma1688(float c[4],
    uint32_t a0, uint32_t a1, uint32_t a2, uint32_t a3,
    uint32_t b0, uint32_t b1)
{
    asm volatile(
        "mma.sync.aligned.m16n8k8.row.col.f32.tf32.tf32.f32 "
        "{%0,%1,%2,%3}, {%4,%5,%6,%7}, {%8,%9}, {%0,%1,%2,%3};"
        : "+f"(c[0]), "+f"(c[1]), "+f"(c[2]), "+f"(c[3])
        : "r"(a0), "r"(a1), "r"(a2), "r"(a3), "r"(b0), "r"(b1));
}

// Two-level grid barrier: 8 groups x 16 blocks. All NBLK blocks co-resident.
__device__ __forceinline__ void grid_barrier() {
    __syncthreads();
    if (threadIdx.x == 0) {
        __threadfence();
        unsigned int g = g_gen;
        unsigned int grp = blockIdx.x & 7u;
        if (atomicAdd(&g_cnt1[grp * 32], 1u) == 15u) {
            if (atomicAdd(&g_cnt2, 1u) == 7u) {
                // last block overall: reset and publish
#pragma unroll
                for (int i = 0; i < 8; ++i) g_cnt1[i * 32] = 0u;
                g_cnt2 = 0u;
                __threadfence();
                g_gen = g + 1u;
            }
        }
        while (g_gen == g) { }
        __threadfence();
    }
    __syncthreads();
}

// =====================================================================
// Input projection GEMM (tf32 tensor cores):
//   Y[m][n] = sum_k X[m][k] * W[n][k] + bi[n]
//   M = T*B = 16384, N = 4096, K = 1024.  Tile 128x128x16, 256 threads.
// =====================================================================
#define GBM 128
#define GBN 128
#define GBK 16
#define ASTR 20   // smem row stride in floats (16 + 4 pad -> conflict-free frags)

__global__ void __launch_bounds__(256, 1) gemm_tc(
    const float* __restrict__ X, const float* __restrict__ W,
    const float* __restrict__ bi, float* __restrict__ Y)
{
    __shared__ float As[2][GBM * ASTR];
    __shared__ float Bs[2][GBN * ASTR];

    const int tid  = threadIdx.x;
    const int warp = tid >> 5;
    const int lane = tid & 31;
    const int g    = lane >> 2;   // groupID 0..7
    const int tig  = lane & 3;    // thread-in-group 0..3
    const int wm   = warp >> 2;   // 0..1  (m)
    const int wn   = warp & 3;    // 0..3  (n)

    const int n0 = blockIdx.x * GBN;
    const int m0 = blockIdx.y * GBM;

    // stage loader: 2 float4 per thread per matrix
    auto stage = [&](int buf, int k0) {
#pragma unroll
        for (int i = 0; i < 2; ++i) {
            int idx = i * 256 + tid;
            int row = idx >> 2;
            int kp  = (idx & 3) * 4;
            uint32_t sa = (uint32_t)__cvta_generic_to_shared(&As[buf][row * ASTR + kp]);
            const float* gpa = X + (size_t)(m0 + row) * HH + k0 + kp;
            asm volatile("cp.async.ca.shared.global [%0], [%1], 16;\n" :: "r"(sa), "l"(gpa));
            uint32_t sb = (uint32_t)__cvta_generic_to_shared(&Bs[buf][row * ASTR + kp]);
            const float* gpb = W + (size_t)(n0 + row) * HH + k0 + kp;
            asm volatile("cp.async.ca.shared.global [%0], [%1], 16;\n" :: "r"(sb), "l"(gpb));
        }
        asm volatile("cp.async.commit_group;\n");
    };

    float C[4][4][4];
#pragma unroll
    for (int a = 0; a < 4; ++a)
#pragma unroll
        for (int b = 0; b < 4; ++b)
#pragma unroll
            for (int c = 0; c < 4; ++c) C[a][b][c] = 0.0f;

    stage(0, 0);

    const int NKT = HH / GBK;   // 64
    for (int kt = 0; kt < NKT; ++kt) {
        if (kt + 1 < NKT) {
            stage((kt + 1) & 1, (kt + 1) * GBK);
            asm volatile("cp.async.wait_group 1;\n" ::: "memory");
        } else {
            asm volatile("cp.async.wait_group 0;\n" ::: "memory");
        }
        __syncthreads();

        const float* as = As[kt & 1];
        const float* bs = Bs[kt & 1];
#pragma unroll
        for (int ks = 0; ks < 2; ++ks) {
            uint32_t af[4][4];
#pragma unroll
            for (int mt = 0; mt < 4; ++mt) {
                int r = wm * 64 + mt * 16 + g;
                int c = ks * 8 + tig;
                af[mt][0] = f2t(as[r * ASTR + c]);
                af[mt][1] = f2t(as[(r + 8) * ASTR + c]);
                af[mt][2] = f2t(as[r * ASTR + c + 4]);
                af[mt][3] = f2t(as[(r + 8) * ASTR + c + 4]);
            }
            uint32_t bf[4][2];
#pragma unroll
            for (int nt = 0; nt < 4; ++nt) {
                int rn = wn * 32 + nt * 8 + g;
                bf[nt][0] = f2t(bs[rn * ASTR + ks * 8 + tig]);
                bf[nt][1] = f2t(bs[rn * ASTR + ks * 8 + tig + 4]);
            }
#pragma unroll
            for (int mt = 0; mt < 4; ++mt)
#pragma unroll
                for (int nt = 0; nt < 4; ++nt)
                    mma1688(C[mt][nt], af[mt][0], af[mt][1], af[mt][2], af[mt][3],
                            bf[nt][0], bf[nt][1]);
        }
        __syncthreads();
    }

    // epilogue: + bias, store
#pragma unroll
    for (int mt = 0; mt < 4; ++mt) {
#pragma unroll
        for (int nt = 0; nt < 4; ++nt) {
            int row = m0 + wm * 64 + mt * 16 + g;
            int col = n0 + wn * 32 + nt * 8 + 2 * tig;
            float b0v = bi[col], b1v = bi[col + 1];
            float2 v0 = make_float2(C[mt][nt][0] + b0v, C[mt][nt][1] + b1v);
            float2 v1 = make_float2(C[mt][nt][2] + b0v, C[mt][nt][3] + b1v);
            *(float2*)(Y + (size_t)row * G4H + col)       = v0;
            *(float2*)(Y + (size_t)(row + 8) * G4H + col) = v1;
        }
    }
}

// =====================================================================
// Persistent recurrent kernel (tf32 tensor cores, R register-resident).
// Block owns 8 n-indices => 32 gate columns {g*1024 + n0 + 0..7}.
// Warp w owns k-chunk [w*128, w*128+128); partials reduced via smem.
// =====================================================================
__global__ void __launch_bounds__(256, 1) recurrent_tc(
    const float* __restrict__ xg,   // [T][B][4H]
    const float* __restrict__ R,    // [4H][H]
    const float* __restrict__ bh,   // [4H]
    const float* __restrict__ h0,   // [B][H]
    const float* __restrict__ c0,   // [B][H]
    float* __restrict__ out,        // [T][B][H]
    float* __restrict__ hT,         // [B][H]
    float* __restrict__ cT)         // [B][H]
{
    __shared__ float part[32 * 296];   // part[b][w][j] : b*296 + w*37 + j

    const int tid  = threadIdx.x;
    const int w    = tid >> 5;
    const int lane = tid & 31;
    const int g    = lane >> 2;
    const int tig  = lane & 3;
    const int n0   = blockIdx.x * 8;

    // Preload R fragments into registers (constant across all timesteps).
    uint32_t Br[4][16][2];
#pragma unroll
    for (int nt = 0; nt < 4; ++nt) {
        const float* rp = R + (size_t)(nt * HH + n0 + g) * HH + w * 128 + tig;
#pragma unroll
        for (int ks = 0; ks < 16; ++ks) {
            Br[nt][ks][0] = f2t(rp[ks * 8]);
            Br[nt][ks][1] = f2t(rp[ks * 8 + 4]);
        }
    }

    // update-phase mapping
    const int ub = tid >> 3;   // b 0..31
    const int un = tid & 7;    // n-offset 0..7
    float bhv[4];
#pragma unroll
    for (int gg = 0; gg < 4; ++gg) bhv[gg] = bh[gg * HH + n0 + un];
    float creg = c0[ub * HH + n0 + un];

    for (int t = 0; t < TT; ++t) {
        const float* hp = (t == 0) ? h0 : g_hbuf[t & 1];

        // prefetch xg for the update phase (DRAM latency hidden behind mma)
        const float* xgt = xg + ((size_t)t * BB + ub) * G4H + n0 + un;
        float xv[4];
#pragma unroll
        for (int gg = 0; gg < 4; ++gg) xv[gg] = __ldg(xgt + gg * HH);

        float Cr[2][4][4];
#pragma unroll
        for (int a = 0; a < 2; ++a)
#pragma unroll
            for (int b = 0; b < 4; ++b)
#pragma unroll
                for (int c = 0; c < 4; ++c) Cr[a][b][c] = 0.0f;

#pragma unroll
        for (int ks = 0; ks < 16; ++ks) {
            int k = w * 128 + ks * 8 + tig;
#pragma unroll
            for (int mt = 0; mt < 2; ++mt) {
                const float* hb = hp + (size_t)(mt * 16 + g) * HH + k;
                // __ldcg: L2-coherent loads (h written by other blocks)
                uint32_t a0 = f2t(__ldcg(hb));
                uint32_t a1 = f2t(__ldcg(hb + 8 * HH));
                uint32_t a2 = f2t(__ldcg(hb + 4));
                uint32_t a3 = f2t(__ldcg(hb + 8 * HH + 4));
#pragma unroll
                for (int nt = 0; nt < 4; ++nt)
                    mma1688(Cr[mt][nt], a0, a1, a2, a3,
                            Br[nt][ks][0], Br[nt][ks][1]);
            }
        }

        // store partials to smem: part[b][w][j]
#pragma unroll
        for (int mt = 0; mt < 2; ++mt) {
#pragma unroll
            for (int nt = 0; nt < 4; ++nt) {
                int b = mt * 16 + g;
                int j = nt * 8 + 2 * tig;
                part[b * 296 + w * 37 + j]           = Cr[mt][nt][0];
                part[b * 296 + w * 37 + j + 1]       = Cr[mt][nt][1];
                part[(b + 8) * 296 + w * 37 + j]     = Cr[mt][nt][2];
                part[(b + 8) * 296 + w * 37 + j + 1] = Cr[mt][nt][3];
            }
        }
        __syncthreads();

        // reduce over 8 warps + gate math. gates order: i, o, z, f
        float gate[4];
#pragma unroll
        for (int gg = 0; gg < 4; ++gg) {
            float s = xv[gg] + bhv[gg];
#pragma unroll
            for (int wi = 0; wi < 8; ++wi)
                s += part[ub * 296 + wi * 37 + gg * 8 + un];
            gate[gg] = sigm(s);
        }
        creg = creg * gate[3] + gate[2] - gate[0];   // c = c*f + z - i
        float hval = sigm(creg) - gate[1];           // h = sigm(c) - o

        out[((size_t)t * BB + ub) * HH + n0 + un] = hval;
        g_hbuf[(t + 1) & 1][ub * HH + n0 + un] = hval;
        if (t == TT - 1) {
            hT[ub * HH + n0 + un] = hval;
            cT[ub * HH + n0 + un] = creg;
        }

        grid_barrier();   // also protects smem `part` reuse
    }
}

// ---------------- launch ----------------
extern "C" void kernel_launch(void* const* d_in, const int* in_sizes, int n_in,
                              void* d_out, int out_size)
{
    (void)in_sizes; (void)n_in; (void)out_size;
    const float* x   = (const float*)d_in[0];
    const float* h0  = (const float*)d_in[1];
    const float* c0  = (const float*)d_in[2];
    const float* W0  = (const float*)d_in[3];
    const float* R0  = (const float*)d_in[4];
    const float* bi0 = (const float*)d_in[5];
    const float* bh0 = (const float*)d_in[6];
    const float* W1  = (const float*)d_in[7];
    const float* R1  = (const float*)d_in[8];
    const float* bi1 = (const float*)d_in[9];
    const float* bh1 = (const float*)d_in[10];

    float* out = (float*)d_out;
    float* hT  = out + (size_t)TT * BB * HH;
    float* cT  = hT + (size_t)2 * BB * HH;

    float* xg = nullptr;  cudaGetSymbolAddress((void**)&xg, g_xg);
    float* x1 = nullptr;  cudaGetSymbolAddress((void**)&x1, g_x1);

    dim3 ggrid(G4H / GBN, (TT * BB) / GBM);   // 32 x 128

    // Layer 0
    gemm_tc<<<ggrid, 256>>>(x, W0, bi0, xg);
    recurrent_tc<<<NBLK, 256>>>(xg, R0, bh0, h0, c0, x1, hT, cT);
    // Layer 1
    gemm_tc<<<ggrid, 256>>>(x1, W1, bi1, xg);
    recurrent_tc<<<NBLK, 256>>>(xg, R1, bh1, h0 + BB * HH, c0 + BB * HH,
                                out, hT + BB * HH, cT + BB * HH);
}

// round 5
// speedup vs baseline: 4.6588x; 1.5232x over previous
#include <cuda_runtime.h>
#include <cstdint>
#include <cstddef>

// Problem constants
#define TT   512
#define BB   32
#define HH   1024
#define G4H  4096
#define NBLK 128           // persistent recurrent grid (co-resident)

// ---------------- scratch ----------------
__device__ float  g_xg[(size_t)TT * BB * G4H];        // input projection (standard [t][b][4H])
__device__ float4 g_xa[(size_t)TT * BB * HH / 4];     // packed-A input X (layer 0)
__device__ float4 g_x1[(size_t)TT * BB * HH / 4];     // packed-A layer-0 output
__device__ float2 g_wb[(size_t)G4H * HH / 2];         // packed-B weights (reused per layer)
__device__ float4 g_hb[2][8192];                      // packed-A hidden state, ping-pong (2x128KB)
__device__ unsigned int          g_cnt1[8 * 32];
__device__ unsigned int          g_cnt2;
__device__ volatile unsigned int g_gen;

__device__ __forceinline__ float sigm(float x) {
    return 1.0f / (1.0f + expf(-x));
}

// fp32 -> tf32 (round-to-nearest) as raw bits
__device__ __forceinline__ uint32_t f2t(float x) {
    uint32_t r;
    asm("cvt.rna.tf32.f32 %0, %1;" : "=r"(r) : "f"(x));
    return r;
}
// fp32 -> tf32-rounded value, returned as float (bit pattern is valid fp32)
__device__ __forceinline__ float f2tf(float x) {
    return __uint_as_float(f2t(x));
}

__device__ __forceinline__ void mma1688(float c[4],
    uint32_t a0, uint32_t a1, uint32_t a2, uint32_t a3,
    uint32_t b0, uint32_t b1)
{
    asm volatile(
        "mma.sync.aligned.m16n8k8.row.col.f32.tf32.tf32.f32 "
        "{%0,%1,%2,%3}, {%4,%5,%6,%7}, {%8,%9}, {%0,%1,%2,%3};"
        : "+f"(c[0]), "+f"(c[1]), "+f"(c[2]), "+f"(c[3])
        : "r"(a0), "r"(a1), "r"(a2), "r"(a3), "r"(b0), "r"(b1));
}

// Two-level grid barrier: 8 groups x 16 blocks. All NBLK blocks co-resident.
__device__ __forceinline__ void grid_barrier() {
    __syncthreads();
    if (threadIdx.x == 0) {
        __threadfence();
        unsigned int g = g_gen;
        unsigned int grp = blockIdx.x & 7u;
        if (atomicAdd(&g_cnt1[grp * 32], 1u) == 15u) {
            if (atomicAdd(&g_cnt2, 1u) == 7u) {
#pragma unroll
                for (int i = 0; i < 8; ++i) g_cnt1[i * 32] = 0u;
                g_cnt2 = 0u;
                __threadfence();
                g_gen = g + 1u;
            }
        }
        while (g_gen == g) { }
        __threadfence();
    }
    __syncthreads();
}

// =====================================================================
// Packing convert kernels (run once per layer; ~tens of us total)
// Packed-A slot s: lane=s&31, ks=(s>>5)&1, mt=(s>>6)&3, wm=(s>>8)&1,
//                  kt=(s>>9)&63, mb=s>>15
//   row r0 = mb*128 + wm*64 + mt*16 + (lane>>2), col c0 = kt*16 + ks*8 + (lane&3)
//   float4 = {X[r0][c0], X[r0+8][c0], X[r0][c0+4], X[r0+8][c0+4]}  (tf32-rounded)
// =====================================================================
__global__ void __launch_bounds__(256) conv_pack_a(
    const float* __restrict__ X, float4* __restrict__ Ap)
{
    int s = blockIdx.x * 256 + threadIdx.x;
    int lane = s & 31, ks = (s >> 5) & 1, mt = (s >> 6) & 3;
    int wm = (s >> 8) & 1, kt = (s >> 9) & 63, mb = s >> 15;
    int r0 = mb * 128 + wm * 64 + mt * 16 + (lane >> 2);
    int c0 = kt * 16 + ks * 8 + (lane & 3);
    const float* p = X + (size_t)r0 * HH + c0;
    float4 v;
    v.x = f2tf(p[0]);
    v.y = f2tf(p[8 * HH]);
    v.z = f2tf(p[4]);
    v.w = f2tf(p[8 * HH + 4]);
    Ap[s] = v;
}

// Packed-B slot s: lane=s&31, ks=(s>>5)&1, nt=(s>>6)&3, wn=(s>>8)&3,
//                  kt=(s>>10)&63, nb=s>>16
//   n = nb*128 + wn*32 + nt*8 + (lane>>2), c0 = kt*16 + ks*8 + (lane&3)
//   float2 = {W[n][c0], W[n][c0+4]}  (tf32-rounded)
__global__ void __launch_bounds__(256) conv_pack_b(
    const float* __restrict__ W, float2* __restrict__ Bp)
{
    int s = blockIdx.x * 256 + threadIdx.x;
    int lane = s & 31, ks = (s >> 5) & 1, nt = (s >> 6) & 3;
    int wn = (s >> 8) & 3, kt = (s >> 10) & 63, nb = s >> 16;
    int n  = nb * 128 + wn * 32 + nt * 8 + (lane >> 2);
    int c0 = kt * 16 + ks * 8 + (lane & 3);
    const float* p = W + (size_t)n * HH + c0;
    Bp[s] = make_float2(f2tf(p[0]), f2tf(p[4]));
}

// =====================================================================
// Input projection GEMM from packed operands. No smem, no cvt.
//   Y[m][n] = sum_k X[m][k]*W[n][k] + bi[n],  M=16384, N=4096, K=1024
//   grid (nb=32, mb=128), 256 threads (8 warps: wm 0..1 x wn 0..3)
// =====================================================================
__global__ void __launch_bounds__(256, 1) gemm_p(
    const float4* __restrict__ Ap, const float2* __restrict__ Bp,
    const float* __restrict__ bi, float* __restrict__ Y)
{
    const int tid  = threadIdx.x;
    const int warp = tid >> 5;
    const int lane = tid & 31;
    const int wm   = warp >> 2;
    const int wn   = warp & 3;
    const int nb   = blockIdx.x;
    const int mb   = blockIdx.y;

    const float4* Ab = Ap + (size_t)mb * 32768;  // 64*2*4*2*32 slots per mb
    const float2* Bb = Bp + (size_t)nb * 65536;  // 64*4*4*2*32 slots per nb

    float C[4][4][4];
#pragma unroll
    for (int a = 0; a < 4; ++a)
#pragma unroll
        for (int b = 0; b < 4; ++b)
#pragma unroll
            for (int c = 0; c < 4; ++c) C[a][b][c] = 0.0f;

    float4 Ar[2][4][2];
    float2 Brr[2][4][2];

#define LOADKT(kt, buf)                                                          \
    {                                                                            \
        _Pragma("unroll")                                                        \
        for (int mt = 0; mt < 4; ++mt)                                           \
            _Pragma("unroll")                                                    \
            for (int ks = 0; ks < 2; ++ks)                                       \
                Ar[buf][mt][ks] = Ab[((((kt) * 2 + wm) * 4 + mt) * 2 + ks) * 32 + lane]; \
        _Pragma("unroll")                                                        \
        for (int nt = 0; nt < 4; ++nt)                                           \
            _Pragma("unroll")                                                    \
            for (int ks = 0; ks < 2; ++ks)                                       \
                Brr[buf][nt][ks] = Bb[((((kt) * 4 + wn) * 4 + nt) * 2 + ks) * 32 + lane]; \
    }

#define COMPUTE(buf)                                                             \
    {                                                                            \
        _Pragma("unroll")                                                        \
        for (int ks = 0; ks < 2; ++ks)                                           \
            _Pragma("unroll")                                                    \
            for (int mt = 0; mt < 4; ++mt) {                                     \
                float4 a = Ar[buf][mt][ks];                                      \
                uint32_t a0 = __float_as_uint(a.x), a1 = __float_as_uint(a.y);   \
                uint32_t a2 = __float_as_uint(a.z), a3 = __float_as_uint(a.w);   \
                _Pragma("unroll")                                                \
                for (int nt = 0; nt < 4; ++nt) {                                 \
                    float2 b = Brr[buf][nt][ks];                                 \
                    mma1688(C[mt][nt], a0, a1, a2, a3,                           \
                            __float_as_uint(b.x), __float_as_uint(b.y));         \
                }                                                                \
            }                                                                    \
    }

    LOADKT(0, 0);
#pragma unroll 1
    for (int kt = 0; kt < 64; kt += 2) {
        LOADKT(kt + 1, 1);
        COMPUTE(0);
        if (kt + 2 < 64) LOADKT(kt + 2, 0);
        COMPUTE(1);
    }
#undef LOADKT
#undef COMPUTE

    const int g = lane >> 2, tig = lane & 3;
#pragma unroll
    for (int mt = 0; mt < 4; ++mt) {
#pragma unroll
        for (int nt = 0; nt < 4; ++nt) {
            int row = mb * 128 + wm * 64 + mt * 16 + g;
            int col = nb * 128 + wn * 32 + nt * 8 + 2 * tig;
            float b0 = bi[col], b1 = bi[col + 1];
            *(float2*)(Y + (size_t)row * G4H + col) =
                make_float2(C[mt][nt][0] + b0, C[mt][nt][1] + b1);
            *(float2*)(Y + (size_t)(row + 8) * G4H + col) =
                make_float2(C[mt][nt][2] + b0, C[mt][nt][3] + b1);
        }
    }
}

// =====================================================================
// Persistent recurrent kernel. h kept in packed-A fragment layout in
// g_hb (tf32-pre-rounded) -> one LDG.128 per fragment, zero cvt.
// HB slot (w, ks16, mt, lane): index ((w*16+ks)*2+mt)*32 + lane
// mode 0: write layer-0 output in packed-A layout to outp (g_x1)
// mode 1: write standard fp32 output to outp (d_out)
// =====================================================================
__global__ void __launch_bounds__(256, 1) recurrent_tc(
    const float* __restrict__ xg,   // [T][B][4H]
    const float* __restrict__ R,    // [4H][H]
    const float* __restrict__ bh,   // [4H]
    const float* __restrict__ h0,   // [B][H]
    const float* __restrict__ c0,   // [B][H]
    float* __restrict__ outp,
    float* __restrict__ hT,         // [B][H]
    float* __restrict__ cT,         // [B][H]
    int mode)
{
    __shared__ float part[32 * 296];   // part[b][w][j] : b*296 + w*37 + j

    const int tid  = threadIdx.x;
    const int w    = tid >> 5;
    const int lane = tid & 31;
    const int g    = lane >> 2;
    const int tig  = lane & 3;
    const int n0   = blockIdx.x * 8;

    // ---- Preload R fragments into registers (constant across timesteps) ----
    uint32_t Br[4][16][2];
#pragma unroll
    for (int nt = 0; nt < 4; ++nt) {
        const float* rp = R + (size_t)(nt * HH + n0 + g) * HH + w * 128 + tig;
#pragma unroll
        for (int ks = 0; ks < 16; ++ks) {
            Br[nt][ks][0] = f2t(__ldg(rp + ks * 8));
            Br[nt][ks][1] = f2t(__ldg(rp + ks * 8 + 4));
        }
    }

    // ---- Convert h0 into packed HB[0] (each block does 64 slots) ----
    if (tid < 64) {
        int slot = blockIdx.x * 64 + tid;            // 0..8191
        int ls = slot & 31, mts = (slot >> 5) & 1;
        int kss = (slot >> 6) & 15, ws = slot >> 10;
        int k0 = ws * 128 + kss * 8 + (ls & 3);
        int b0 = mts * 16 + (ls >> 2);
        float4 v;
        v.x = f2tf(h0[b0 * HH + k0]);
        v.y = f2tf(h0[(b0 + 8) * HH + k0]);
        v.z = f2tf(h0[b0 * HH + k0 + 4]);
        v.w = f2tf(h0[(b0 + 8) * HH + k0 + 4]);
        g_hb[0][slot] = v;
    }

    // ---- update-phase constants ----
    const int ub = tid >> 3;   // b 0..31
    const int un = tid & 7;    // n-offset 0..7
    const int hid = n0 + un;   // global hidden index
    float bhv[4];
#pragma unroll
    for (int gg = 0; gg < 4; ++gg) bhv[gg] = bh[gg * HH + hid];
    float creg = c0[ub * HH + hid];

    // HB write slot for (ub, hid): constant across t (only buffer alternates)
    {
        // computed below inline each step via precomputed offsets
    }
    const int hw_w = hid >> 7, hw_ks = (hid >> 3) & 15, hw_tig = hid & 3;
    const int hw_half = (hid >> 2) & 1;
    const int hw_mt = ub >> 4, hw_g = ub & 7, hw_rh = (ub >> 3) & 1;
    const int hb_slot = ((hw_w * 16 + hw_ks) * 2 + hw_mt) * 32 + hw_g * 4 + hw_tig;
    const int hb_elem = hw_half * 2 + hw_rh;
    float* hb_w[2] = { (float*)&g_hb[0][hb_slot] + hb_elem,
                       (float*)&g_hb[1][hb_slot] + hb_elem };

    grid_barrier();   // HB[0] ready everywhere

    for (int t = 0; t < TT; ++t) {
        const float4* hp = g_hb[t & 1];

        // prefetch xg for update phase
        const float* xgt = xg + ((size_t)t * BB + ub) * G4H + hid;
        float xv[4];
#pragma unroll
        for (int gg = 0; gg < 4; ++gg) xv[gg] = __ldg(xgt + gg * HH);

        float Cr[2][4][4];
#pragma unroll
        for (int a = 0; a < 2; ++a)
#pragma unroll
            for (int b = 0; b < 4; ++b)
#pragma unroll
                for (int c = 0; c < 4; ++c) Cr[a][b][c] = 0.0f;

        // 4-deep pipelined fragment loads (LDG.128, L2-coherent), mma chain
        float4 Ab[4][2];
#pragma unroll
        for (int p = 0; p < 4; ++p) {
#pragma unroll
            for (int mt = 0; mt < 2; ++mt)
                Ab[p][mt] = __ldcg(&hp[((w * 16 + p) * 2 + mt) * 32 + lane]);
        }
#pragma unroll
        for (int ks = 0; ks < 16; ++ks) {
            const int pb = ks & 3;
            float4 a0 = Ab[pb][0];
            float4 a1 = Ab[pb][1];
            if (ks + 4 < 16) {
#pragma unroll
                for (int mt = 0; mt < 2; ++mt)
                    Ab[pb][mt] = __ldcg(&hp[((w * 16 + (ks + 4)) * 2 + mt) * 32 + lane]);
            }
            uint32_t u00 = __float_as_uint(a0.x), u01 = __float_as_uint(a0.y);
            uint32_t u02 = __float_as_uint(a0.z), u03 = __float_as_uint(a0.w);
            uint32_t u10 = __float_as_uint(a1.x), u11 = __float_as_uint(a1.y);
            uint32_t u12 = __float_as_uint(a1.z), u13 = __float_as_uint(a1.w);
#pragma unroll
            for (int nt = 0; nt < 4; ++nt) {
                mma1688(Cr[0][nt], u00, u01, u02, u03, Br[nt][ks][0], Br[nt][ks][1]);
                mma1688(Cr[1][nt], u10, u11, u12, u13, Br[nt][ks][0], Br[nt][ks][1]);
            }
        }

        // store partials to smem: part[b][w][j]
#pragma unroll
        for (int mt = 0; mt < 2; ++mt) {
#pragma unroll
            for (int nt = 0; nt < 4; ++nt) {
                int b = mt * 16 + g;
                int j = nt * 8 + 2 * tig;
                part[b * 296 + w * 37 + j]           = Cr[mt][nt][0];
                part[b * 296 + w * 37 + j + 1]       = Cr[mt][nt][1];
                part[(b + 8) * 296 + w * 37 + j]     = Cr[mt][nt][2];
                part[(b + 8) * 296 + w * 37 + j + 1] = Cr[mt][nt][3];
            }
        }
        __syncthreads();

        // reduce over 8 warps + gate math. gates order: i, o, z, f
        float gate[4];
#pragma unroll
        for (int gg = 0; gg < 4; ++gg) {
            float s = xv[gg] + bhv[gg];
#pragma unroll
            for (int wi = 0; wi < 8; ++wi)
                s += part[ub * 296 + wi * 37 + gg * 8 + un];
            gate[gg] = sigm(s);
        }
        creg = creg * gate[3] + gate[2] - gate[0];   // c = c*f + z - i
        float hval = sigm(creg) - gate[1];           // h = sigm(c) - o

        // output store
        if (mode == 0) {
            // packed-A layout (feeds layer-1 gemm); tf32-rounded
            int m = t * BB + ub;
            int mb = m >> 7, r = m & 127;
            int wm_ = r >> 6, mt_ = (r >> 4) & 3, rh_ = (r >> 3) & 1, g_ = r & 7;
            int kt_ = hid >> 4, ks_ = (hid >> 3) & 1;
            int half_ = (hid >> 2) & 1, tig_ = hid & 3;
            size_t slot = ((((size_t)(mb * 64 + kt_) * 2 + wm_) * 4 + mt_) * 2 + ks_) * 32
                          + g_ * 4 + tig_;
            outp[slot * 4 + half_ * 2 + rh_] = f2tf(hval);
        } else {
            outp[((size_t)t * BB + ub) * HH + hid] = hval;
        }

        // HB store for next step (tf32-rounded)
        *hb_w[(t + 1) & 1] = f2tf(hval);

        if (t == TT - 1) {
            hT[ub * HH + hid] = hval;
            cT[ub * HH + hid] = creg;
        }

        grid_barrier();
    }
}

// ---------------- launch ----------------
extern "C" void kernel_launch(void* const* d_in, const int* in_sizes, int n_in,
                              void* d_out, int out_size)
{
    (void)in_sizes; (void)n_in; (void)out_size;
    const float* x   = (const float*)d_in[0];
    const float* h0  = (const float*)d_in[1];
    const float* c0  = (const float*)d_in[2];
    const float* W0  = (const float*)d_in[3];
    const float* R0  = (const float*)d_in[4];
    const float* bi0 = (const float*)d_in[5];
    const float* bh0 = (const float*)d_in[6];
    const float* W1  = (const float*)d_in[7];
    const float* R1  = (const float*)d_in[8];
    const float* bi1 = (const float*)d_in[9];
    const float* bh1 = (const float*)d_in[10];

    float* out = (float*)d_out;
    float* hT  = out + (size_t)TT * BB * HH;
    float* cT  = hT + (size_t)2 * BB * HH;

    float*  xg = nullptr;  cudaGetSymbolAddress((void**)&xg, g_xg);
    float4* xa = nullptr;  cudaGetSymbolAddress((void**)&xa, g_xa);
    float4* x1 = nullptr;  cudaGetSymbolAddress((void**)&x1, g_x1);
    float2* wb = nullptr;  cudaGetSymbolAddress((void**)&wb, g_wb);

    const int aslots = TT * BB * HH / 4;   // 4,194,304
    const int bslots = G4H * HH / 2;       // 2,097,152
    dim3 ggrid(G4H / 128, (TT * BB) / 128);  // (32, 128)

    // Layer 0
    conv_pack_a<<<aslots / 256, 256>>>(x, xa);
    conv_pack_b<<<bslots / 256, 256>>>(W0, wb);
    gemm_p<<<ggrid, 256>>>(xa, wb, bi0, xg);
    recurrent_tc<<<NBLK, 256>>>(xg, R0, bh0, h0, c0, (float*)x1, hT, cT, 0);
    // Layer 1
    conv_pack_b<<<bslots / 256, 256>>>(W1, wb);
    gemm_p<<<ggrid, 256>>>(x1, wb, bi1, xg);
    recurrent_tc<<<NBLK, 256>>>(xg, R1, bh1, h0 + BB * HH, c0 + BB * HH,
                                out, hT + BB * HH, cT + BB * HH, 1);
}